// round 1
// baseline (speedup 1.0000x reference)
#include <cuda_runtime.h>
#include <cuda_bf16.h>
#include <math.h>

// Problem constants
#define Bn   32
#define Ln   36864
#define Cn   16
#define Dn   512
#define Kn   24
#define LOUT 1536
#define Mtot (Bn * LOUT)      // 49152
#define KDIM 384              // C*K reduction dim

// -------- scratch (device globals; no allocation allowed) --------
__device__ float g_woffT[48 * KDIM];          // [o][k*16+c]
__device__ float g_wdefT[Dn * KDIM];          // [d][k*16+c]
__device__ float g_val[(size_t)Mtot * KDIM];  // sampled values, 75.5 MB
__device__ int   g_i0[Mtot * Kn];
__device__ float g_w0[Mtot * Kn];
__device__ float g_w1[Mtot * Kn];

// ---------------- kernel 0: weight transposes ----------------
// woffT[o][k*16+c] = w_off[(o*16+c)*24+k]; wdefT[d][k*16+c] = w_def[(d*16+c)*24+k]
__global__ void k_prep(const float* __restrict__ w_off, const float* __restrict__ w_def) {
    int idx = blockIdx.x * 256 + threadIdx.x;   // total 48*384 + 512*384 = 215040
    if (idx < 48 * KDIM) {
        int o = idx / KDIM, i = idx - o * KDIM;
        int k = i >> 4, c = i & 15;
        g_woffT[idx] = w_off[(o * 16 + c) * 24 + k];
    } else {
        int j = idx - 48 * KDIM;
        int d = j / KDIM, i = j - d * KDIM;
        int k = i >> 4, c = i & 15;
        g_wdefT[j] = w_def[(d * 16 + c) * 24 + k];
    }
}

// ---------------- kernel 1: offset GEMM + sampling metadata ----------------
// off[m][o] = sum_i x[m*384+i] * woffT[o][i] + b_off[o]
// then per (m,k): i0, w0, w1  (bilinear weights with masks & wy folded in)
__global__ __launch_bounds__(256) void k_offsets(const float* __restrict__ x,
                                                 const float* __restrict__ b_off) {
    __shared__ float sA[64][33];
    __shared__ float sB[48][33];
    __shared__ float sOff[64][49];

    int mBase = blockIdx.x * 64;
    int tid = threadIdx.x;
    int tr = tid & 15;        // row lane: rows tr, tr+16, tr+32, tr+48
    int tc = tid >> 4;        // col group: cols tc*3 .. tc*3+2
    float acc[4][3] = {};

    const float* Ax = x + (size_t)mBase * KDIM;   // window view == x reshaped

    for (int k0 = 0; k0 < KDIM; k0 += 32) {
        #pragma unroll
        for (int j = 0; j < 8; j++) {             // A: 64x32
            int e = tid + j * 256;
            int row = e >> 5, col = e & 31;
            sA[row][col] = Ax[row * KDIM + k0 + col];
        }
        #pragma unroll
        for (int j = 0; j < 6; j++) {             // B: 48x32
            int e = tid + j * 256;
            int o = e >> 5, col = e & 31;
            sB[o][col] = g_woffT[o * KDIM + k0 + col];
        }
        __syncthreads();
        #pragma unroll
        for (int kk = 0; kk < 32; kk++) {
            float a[4], bb[3];
            #pragma unroll
            for (int j = 0; j < 4; j++) a[j] = sA[tr + 16 * j][kk];
            #pragma unroll
            for (int i = 0; i < 3; i++) bb[i] = sB[tc * 3 + i][kk];
            #pragma unroll
            for (int j = 0; j < 4; j++)
                #pragma unroll
                for (int i = 0; i < 3; i++)
                    acc[j][i] += a[j] * bb[i];
        }
        __syncthreads();
    }

    #pragma unroll
    for (int j = 0; j < 4; j++)
        #pragma unroll
        for (int i = 0; i < 3; i++) {
            int o = tc * 3 + i;
            sOff[tr + 16 * j][o] = acc[j][i] + b_off[o];
        }
    __syncthreads();

    // metadata: 64 rows * 24 taps = 1536 items
    #pragma unroll
    for (int j = 0; j < 6; j++) {
        int e = tid + j * 256;
        int r = e / 24, k = e - r * 24;
        int m = mBase + r;
        int lo = m % LOUT;
        float dy = sOff[r][2 * k];
        float dx = sOff[r][2 * k + 1];
        float px = (float)(lo * Kn + k) + dx;
        float wy = fmaxf(0.0f, 1.0f - fabsf(dy));
        float x0 = floorf(px);
        float lw = px - x0;
        int i0 = (int)x0;
        bool valid = (px > -1.0f) && (px < (float)Ln);
        float w0 = (valid && i0 >= 0 && i0 < Ln) ? (1.0f - lw) * wy : 0.0f;
        float w1 = (valid && (i0 + 1) >= 0 && (i0 + 1) < Ln) ? lw * wy : 0.0f;
        int idx = m * Kn + k;
        g_i0[idx] = i0;
        g_w0[idx] = w0;
        g_w1[idx] = w1;
    }
}

// ---------------- kernel 2: bilinear sampling -> g_val[M][k*16+c] ----------------
__global__ void k_sample(const float* __restrict__ x) {
    int gid = blockIdx.x * 256 + threadIdx.x;   // total Mtot*384
    int m = gid / KDIM;
    int rem = gid - m * KDIM;                   // rem = k*16 + c
    int k = rem >> 4;
    int c = rem & 15;
    int idx = m * Kn + k;
    int i0 = g_i0[idx];
    float w0 = g_w0[idx];
    float w1 = g_w1[idx];
    int b = m / LOUT;
    int base = b * (Ln * Cn);
    int a0 = max(0, min(i0, Ln - 1));
    int a1 = max(0, min(i0 + 1, Ln - 1));
    float v0 = __ldg(x + base + a0 * Cn + c);
    float v1 = __ldg(x + base + a1 * Cn + c);
    g_val[gid] = w0 * v0 + w1 * v1;
}

// ---------------- kernel 3: main GEMM: out[m][d] = val[m][:] . wdefT[d][:] + b_def[d] ----
#define BM 128
#define BN 128
#define BK 16

__global__ __launch_bounds__(256, 2) void k_gemm(const float* __restrict__ b_def,
                                                 float* __restrict__ out) {
    __shared__ float As[BK][BM + 4];
    __shared__ float Bs[BK][BN + 4];

    int mBase = blockIdx.y * BM;
    int nBase = blockIdx.x * BN;
    int tid = threadIdx.x;
    int tx = tid & 15;       // -> cols tx*8..tx*8+7
    int ty = tid >> 4;       // -> rows ty*8..ty*8+7
    float acc[8][8] = {};

    const float* Aptr = g_val + (size_t)mBase * KDIM;
    const float* Bptr = g_wdefT + (size_t)nBase * KDIM;

    for (int k0 = 0; k0 < KDIM; k0 += BK) {
        #pragma unroll
        for (int j = 0; j < 2; j++) {
            int e = tid + j * 256;        // 0..511 -> 128 rows x 4 float4
            int row = e >> 2;
            int kc4 = (e & 3) * 4;
            float4 v = *(const float4*)(Aptr + (size_t)row * KDIM + k0 + kc4);
            As[kc4 + 0][row] = v.x; As[kc4 + 1][row] = v.y;
            As[kc4 + 2][row] = v.z; As[kc4 + 3][row] = v.w;
            float4 w = *(const float4*)(Bptr + (size_t)row * KDIM + k0 + kc4);
            Bs[kc4 + 0][row] = w.x; Bs[kc4 + 1][row] = w.y;
            Bs[kc4 + 2][row] = w.z; Bs[kc4 + 3][row] = w.w;
        }
        __syncthreads();
        #pragma unroll
        for (int kk = 0; kk < BK; kk++) {
            float a[8], b[8];
            *(float4*)&a[0] = *(const float4*)&As[kk][ty * 8];
            *(float4*)&a[4] = *(const float4*)&As[kk][ty * 8 + 4];
            *(float4*)&b[0] = *(const float4*)&Bs[kk][tx * 8];
            *(float4*)&b[4] = *(const float4*)&Bs[kk][tx * 8 + 4];
            #pragma unroll
            for (int i = 0; i < 8; i++)
                #pragma unroll
                for (int j2 = 0; j2 < 8; j2++)
                    acc[i][j2] += a[i] * b[j2];
        }
        __syncthreads();
    }

    #pragma unroll
    for (int i = 0; i < 8; i++) {
        int m = mBase + ty * 8 + i;
        #pragma unroll
        for (int j = 0; j < 8; j += 4) {
            int n = nBase + tx * 8 + j;
            float4 r;
            r.x = acc[i][j + 0] + b_def[n + 0];
            r.y = acc[i][j + 1] + b_def[n + 1];
            r.z = acc[i][j + 2] + b_def[n + 2];
            r.w = acc[i][j + 3] + b_def[n + 3];
            *(float4*)(out + (size_t)m * Dn + n) = r;
        }
    }
}

// ---------------- launch ----------------
extern "C" void kernel_launch(void* const* d_in, const int* in_sizes, int n_in,
                              void* d_out, int out_size) {
    const float* x     = (const float*)d_in[0];
    const float* w_off = (const float*)d_in[1];
    const float* b_off = (const float*)d_in[2];
    const float* w_def = (const float*)d_in[3];
    const float* b_def = (const float*)d_in[4];
    float* out = (float*)d_out;

    (void)in_sizes; (void)n_in; (void)out_size;

    k_prep<<<(48 * KDIM + Dn * KDIM) / 256, 256>>>(w_off, w_def);
    k_offsets<<<Mtot / 64, 256>>>(x, b_off);
    k_sample<<<((size_t)Mtot * KDIM) / 256, 256>>>(x);
    k_gemm<<<dim3(Dn / BN, Mtot / BM), 256>>>(b_def, out);
}

// round 3
// speedup vs baseline: 1.8567x; 1.8567x over previous
#include <cuda_runtime.h>
#include <cuda_bf16.h>
#include <math.h>

// Problem constants
#define Bn   32
#define Ln   36864
#define Cn   16
#define Dn   512
#define Kn   24
#define LOUT 1536
#define Mtot (Bn * LOUT)      // 49152
#define KDIM 384              // C*K reduction dim

// -------- scratch (device globals; no allocation allowed) --------
__device__ float g_woffT[48 * KDIM];          // [o][k*16+c]
__device__ float g_wdefT[Dn * KDIM];          // [d][k*16+c]
__device__ float g_val[(size_t)Mtot * KDIM];  // sampled values, 75.5 MB
__device__ int   g_i0[Mtot * Kn];
__device__ float g_w0[Mtot * Kn];
__device__ float g_w1[Mtot * Kn];

// ---------------- kernel 0: weight transposes ----------------
__global__ void k_prep(const float* __restrict__ w_off, const float* __restrict__ w_def) {
    int idx = blockIdx.x * 256 + threadIdx.x;   // total 48*384 + 512*384
    if (idx < 48 * KDIM) {
        int o = idx / KDIM, i = idx - o * KDIM;
        int k = i >> 4, c = i & 15;
        g_woffT[idx] = w_off[(o * 16 + c) * 24 + k];
    } else {
        int j = idx - 48 * KDIM;
        int d = j / KDIM, i = j - d * KDIM;
        int k = i >> 4, c = i & 15;
        g_wdefT[j] = w_def[(d * 16 + c) * 24 + k];
    }
}

// ---------------- kernel 1: offset GEMM + sampling metadata ----------------
__global__ __launch_bounds__(256) void k_offsets(const float* __restrict__ x,
                                                 const float* __restrict__ b_off) {
    __shared__ float sA[64][33];
    __shared__ float sB[48][33];
    __shared__ float sOff[64][49];

    int mBase = blockIdx.x * 64;
    int tid = threadIdx.x;
    int tr = tid & 15;
    int tc = tid >> 4;
    float acc[4][3] = {};

    const float* Ax = x + (size_t)mBase * KDIM;

    for (int k0 = 0; k0 < KDIM; k0 += 32) {
        #pragma unroll
        for (int j = 0; j < 8; j++) {
            int e = tid + j * 256;
            int row = e >> 5, col = e & 31;
            sA[row][col] = Ax[row * KDIM + k0 + col];
        }
        #pragma unroll
        for (int j = 0; j < 6; j++) {
            int e = tid + j * 256;
            int o = e >> 5, col = e & 31;
            sB[o][col] = g_woffT[o * KDIM + k0 + col];
        }
        __syncthreads();
        #pragma unroll
        for (int kk = 0; kk < 32; kk++) {
            float a[4], bb[3];
            #pragma unroll
            for (int j = 0; j < 4; j++) a[j] = sA[tr + 16 * j][kk];
            #pragma unroll
            for (int i = 0; i < 3; i++) bb[i] = sB[tc * 3 + i][kk];
            #pragma unroll
            for (int j = 0; j < 4; j++)
                #pragma unroll
                for (int i = 0; i < 3; i++)
                    acc[j][i] += a[j] * bb[i];
        }
        __syncthreads();
    }

    #pragma unroll
    for (int j = 0; j < 4; j++)
        #pragma unroll
        for (int i = 0; i < 3; i++) {
            int o = tc * 3 + i;
            sOff[tr + 16 * j][o] = acc[j][i] + b_off[o];
        }
    __syncthreads();

    #pragma unroll
    for (int j = 0; j < 6; j++) {
        int e = tid + j * 256;
        int r = e / 24, k = e - r * 24;
        int m = mBase + r;
        int lo = m % LOUT;
        float dy = sOff[r][2 * k];
        float dx = sOff[r][2 * k + 1];
        float px = (float)(lo * Kn + k) + dx;
        float wy = fmaxf(0.0f, 1.0f - fabsf(dy));
        float x0 = floorf(px);
        float lw = px - x0;
        int i0 = (int)x0;
        bool valid = (px > -1.0f) && (px < (float)Ln);
        float w0 = (valid && i0 >= 0 && i0 < Ln) ? (1.0f - lw) * wy : 0.0f;
        float w1 = (valid && (i0 + 1) >= 0 && (i0 + 1) < Ln) ? lw * wy : 0.0f;
        int idx = m * Kn + k;
        g_i0[idx] = i0;
        g_w0[idx] = w0;
        g_w1[idx] = w1;
    }
}

// ---------------- kernel 2: bilinear sampling -> g_val[M][k*16+c] ----------------
__global__ void k_sample(const float* __restrict__ x) {
    int gid = blockIdx.x * 256 + threadIdx.x;
    int m = gid / KDIM;
    int rem = gid - m * KDIM;
    int k = rem >> 4;
    int c = rem & 15;
    int idx = m * Kn + k;
    int i0 = g_i0[idx];
    float w0 = g_w0[idx];
    float w1 = g_w1[idx];
    int b = m / LOUT;
    int base = b * (Ln * Cn);
    int a0 = max(0, min(i0, Ln - 1));
    int a1 = max(0, min(i0 + 1, Ln - 1));
    float v0 = __ldg(x + base + a0 * Cn + c);
    float v1 = __ldg(x + base + a1 * Cn + c);
    g_val[gid] = w0 * v0 + w1 * v1;
}

// ---------------- kernel 3: tf32 tensor-core GEMM ----------------
// out[m][d] = val[m][:] . wdefT[d][:] + b_def[d]
#define BM 128
#define BN 128
#define BK 16
#define SPAD 20   // row stride in smem floats (conflict-free: (20g+c)%32 covers all banks)

__device__ __forceinline__ unsigned f2tf32(float f) {
    unsigned r;
    asm("cvt.rna.tf32.f32 %0, %1;" : "=r"(r) : "f"(f));
    return r;
}

__global__ __launch_bounds__(256, 2) void k_gemm_tc(const float* __restrict__ b_def,
                                                    float* __restrict__ out) {
    __shared__ unsigned sA[2][BM * SPAD];
    __shared__ unsigned sB[2][BN * SPAD];

    int tid  = threadIdx.x;
    int lane = tid & 31;
    int wid  = tid >> 5;
    int wm = wid & 3;        // warp m index: tile m offset wm*32
    int wn = wid >> 2;       // warp n index: tile n offset wn*64
    int g  = lane >> 2;      // group 0..7
    int cc = lane & 3;       // 0..3

    int mBase = blockIdx.y * BM;
    int nBase = blockIdx.x * BN;

    const float* Ag = g_val  + (size_t)mBase * KDIM;
    const float* Bg = g_wdefT + (size_t)nBase * KDIM;

    // per-thread gmem load mapping: idx = tid + j*256 (j=0,1); row = idx>>2, c4 = (idx&3)*4
    int ldRow0 = tid >> 2,        ldC0 = (tid & 3) * 4;
    int ldRow1 = (tid + 256) >> 2, ldC1 = ((tid + 256) & 3) * 4;

    float4 pa0, pa1, pb0, pb1;

    auto loadG = [&](int k0) {
        pa0 = *(const float4*)(Ag + (size_t)ldRow0 * KDIM + k0 + ldC0);
        pa1 = *(const float4*)(Ag + (size_t)ldRow1 * KDIM + k0 + ldC1);
        pb0 = *(const float4*)(Bg + (size_t)ldRow0 * KDIM + k0 + ldC0);
        pb1 = *(const float4*)(Bg + (size_t)ldRow1 * KDIM + k0 + ldC1);
    };
    auto stsStage = [&](int s) {
        unsigned* a = &sA[s][0];
        unsigned* b = &sB[s][0];
        int o0 = ldRow0 * SPAD + ldC0;
        int o1 = ldRow1 * SPAD + ldC1;
        a[o0+0] = f2tf32(pa0.x); a[o0+1] = f2tf32(pa0.y); a[o0+2] = f2tf32(pa0.z); a[o0+3] = f2tf32(pa0.w);
        a[o1+0] = f2tf32(pa1.x); a[o1+1] = f2tf32(pa1.y); a[o1+2] = f2tf32(pa1.z); a[o1+3] = f2tf32(pa1.w);
        b[o0+0] = f2tf32(pb0.x); b[o0+1] = f2tf32(pb0.y); b[o0+2] = f2tf32(pb0.z); b[o0+3] = f2tf32(pb0.w);
        b[o1+0] = f2tf32(pb1.x); b[o1+1] = f2tf32(pb1.y); b[o1+2] = f2tf32(pb1.z); b[o1+3] = f2tf32(pb1.w);
    };

    float acc[2][8][4];
    #pragma unroll
    for (int i = 0; i < 2; i++)
        #pragma unroll
        for (int j = 0; j < 8; j++)
            #pragma unroll
            for (int q = 0; q < 4; q++) acc[i][j][q] = 0.0f;

    loadG(0);
    stsStage(0);
    __syncthreads();

    #pragma unroll 1
    for (int ch = 0; ch < KDIM / BK; ch++) {
        int s = ch & 1;
        if (ch + 1 < KDIM / BK) loadG((ch + 1) * BK);

        const unsigned* a = &sA[s][0];
        const unsigned* b = &sB[s][0];
        #pragma unroll
        for (int ks = 0; ks < 2; ks++) {
            int kb = ks * 8;
            unsigned af[2][4];
            #pragma unroll
            for (int mt = 0; mt < 2; mt++) {
                int r0 = wm * 32 + mt * 16 + g;
                af[mt][0] = a[r0 * SPAD + kb + cc];
                af[mt][1] = a[(r0 + 8) * SPAD + kb + cc];
                af[mt][2] = a[r0 * SPAD + kb + cc + 4];
                af[mt][3] = a[(r0 + 8) * SPAD + kb + cc + 4];
            }
            unsigned bf[8][2];
            #pragma unroll
            for (int nt = 0; nt < 8; nt++) {
                int n = wn * 64 + nt * 8 + g;
                bf[nt][0] = b[n * SPAD + kb + cc];
                bf[nt][1] = b[n * SPAD + kb + cc + 4];
            }
            #pragma unroll
            for (int mt = 0; mt < 2; mt++)
                #pragma unroll
                for (int nt = 0; nt < 8; nt++) {
                    asm volatile(
                        "mma.sync.aligned.m16n8k8.row.col.f32.tf32.tf32.f32 "
                        "{%0,%1,%2,%3}, {%4,%5,%6,%7}, {%8,%9}, {%0,%1,%2,%3};\n"
                        : "+f"(acc[mt][nt][0]), "+f"(acc[mt][nt][1]),
                          "+f"(acc[mt][nt][2]), "+f"(acc[mt][nt][3])
                        : "r"(af[mt][0]), "r"(af[mt][1]), "r"(af[mt][2]), "r"(af[mt][3]),
                          "r"(bf[nt][0]), "r"(bf[nt][1]));
                }
        }

        if (ch + 1 < KDIM / BK) {
            stsStage(s ^ 1);
            __syncthreads();
        }
    }

    // epilogue: c0/c1 -> (row=g, col=2cc..2cc+1); c2/c3 -> row g+8
    #pragma unroll
    for (int mt = 0; mt < 2; mt++) {
        int r0 = mBase + wm * 32 + mt * 16 + g;
        #pragma unroll
        for (int nt = 0; nt < 8; nt++) {
            int col = nBase + wn * 64 + nt * 8 + 2 * cc;
            float bz0 = __ldg(b_def + col);
            float bz1 = __ldg(b_def + col + 1);
            float2 v0 = make_float2(acc[mt][nt][0] + bz0, acc[mt][nt][1] + bz1);
            float2 v1 = make_float2(acc[mt][nt][2] + bz0, acc[mt][nt][3] + bz1);
            *(float2*)(out + (size_t)r0 * Dn + col) = v0;
            *(float2*)(out + (size_t)(r0 + 8) * Dn + col) = v1;
        }
    }
}

// ---------------- launch ----------------
extern "C" void kernel_launch(void* const* d_in, const int* in_sizes, int n_in,
                              void* d_out, int out_size) {
    const float* x     = (const float*)d_in[0];
    const float* w_off = (const float*)d_in[1];
    const float* b_off = (const float*)d_in[2];
    const float* w_def = (const float*)d_in[3];
    const float* b_def = (const float*)d_in[4];
    float* out = (float*)d_out;

    (void)in_sizes; (void)n_in; (void)out_size;

    k_prep<<<(48 * KDIM + Dn * KDIM) / 256, 256>>>(w_off, w_def);
    k_offsets<<<Mtot / 64, 256>>>(x, b_off);
    k_sample<<<((size_t)Mtot * KDIM) / 256, 256>>>(x);
    k_gemm_tc<<<dim3(Dn / BN, Mtot / BM), 256>>>(b_def, out);
}

// round 5
// speedup vs baseline: 2.2514x; 1.2125x over previous
#include <cuda_runtime.h>
#include <cuda_bf16.h>
#include <math.h>

// Problem constants
#define Bn   32
#define Ln   36864
#define Cn   16
#define Dn   512
#define Kn   24
#define LOUT 1536
#define Mtot (Bn * LOUT)      // 49152
#define KDIM 384              // C*K reduction dim
#define SPAD 20               // smem row stride (conflict-free for mma frag reads)

// -------- scratch (device globals) --------
__device__ unsigned g_woffT[48 * KDIM];       // tf32-converted [o][k*16+c]
__device__ unsigned g_wdefT[Dn * KDIM];       // tf32-converted [d][k*16+c]
__device__ int   g_i0[Mtot * Kn];
__device__ float g_w0[Mtot * Kn];
__device__ float g_w1[Mtot * Kn];

__device__ __forceinline__ unsigned f2tf32(float f) {
    unsigned r;
    asm("cvt.rna.tf32.f32 %0, %1;" : "=r"(r) : "f"(f));
    return r;
}
__device__ __forceinline__ unsigned sptr(const void* p) {
    return (unsigned)__cvta_generic_to_shared(p);
}

#define MMA_TF32(acc, af, bf)                                                  \
    asm volatile(                                                              \
        "mma.sync.aligned.m16n8k8.row.col.f32.tf32.tf32.f32 "                  \
        "{%0,%1,%2,%3}, {%4,%5,%6,%7}, {%8,%9}, {%0,%1,%2,%3};\n"              \
        : "+f"(acc[0]), "+f"(acc[1]), "+f"(acc[2]), "+f"(acc[3])               \
        : "r"(af[0]), "r"(af[1]), "r"(af[2]), "r"(af[3]),                      \
          "r"(bf[0]), "r"(bf[1]))

// ---------------- kernel 0: weight transpose + tf32 convert ----------------
__global__ void k_prep(const float* __restrict__ w_off, const float* __restrict__ w_def) {
    int idx = blockIdx.x * 256 + threadIdx.x;   // 48*384 + 512*384 = 215040
    if (idx < 48 * KDIM) {
        int o = idx / KDIM, i = idx - o * KDIM;
        int k = i >> 4, c = i & 15;
        g_woffT[idx] = f2tf32(w_off[(o * 16 + c) * 24 + k]);
    } else {
        int j = idx - 48 * KDIM;
        int d = j / KDIM, i = j - d * KDIM;
        int k = i >> 4, c = i & 15;
        g_wdefT[j] = f2tf32(w_def[(d * 16 + c) * 24 + k]);
    }
}

// ---------------- kernel 1: offset GEMM (tf32 TC) + metadata epilogue ------
// off[m][o] = x_flat[m][:] . woffT[o][:] + b_off[o]; then per (m,k) -> i0,w0,w1
// 8 warps, each owns a 16-row m-tile; N=48 = 6 n-tiles of 8.
__global__ __launch_bounds__(256) void k_offsets_tc(const float* __restrict__ x,
                                                    const float* __restrict__ b_off) {
    __shared__ unsigned sA[2][128 * SPAD];
    __shared__ unsigned sB[2][48 * SPAD];

    int tid = threadIdx.x, lane = tid & 31, wid = tid >> 5;
    int g = lane >> 2, cc = lane & 3;
    int mBase = blockIdx.x * 128;
    const float* Ax = x + (size_t)mBase * KDIM;
    int r = tid >> 1, h = tid & 1;      // A staging: row r, channels h*8..h*8+7

    float4 xa, xb2;
    auto loadA = [&](int ch) {
        const float4* p = (const float4*)(Ax + (size_t)r * KDIM + ch * 16 + h * 8);
        xa = p[0]; xb2 = p[1];
    };
    auto stsA = [&](int s) {
        unsigned* dst = &sA[s][r * SPAD + h * 8];
        uint4 q0 = make_uint4(f2tf32(xa.x),  f2tf32(xa.y),  f2tf32(xa.z),  f2tf32(xa.w));
        uint4 q1 = make_uint4(f2tf32(xb2.x), f2tf32(xb2.y), f2tf32(xb2.z), f2tf32(xb2.w));
        *(uint4*)dst = q0;
        *(uint4*)(dst + 4) = q1;
    };
    auto cpB = [&](int ch, int s) {
        if (tid < 192) {                 // 48 rows x 16 cols = 192 float4
            int row = tid >> 2, c4 = (tid & 3) * 4;
            unsigned d = sptr(&sB[s][row * SPAD + c4]);
            const unsigned* src = &g_woffT[row * KDIM + ch * 16 + c4];
            asm volatile("cp.async.cg.shared.global [%0], [%1], 16;\n" :: "r"(d), "l"(src));
        }
        asm volatile("cp.async.commit_group;\n");
    };

    float acc[6][4];
    #pragma unroll
    for (int i = 0; i < 6; i++)
        #pragma unroll
        for (int q = 0; q < 4; q++) acc[i][q] = 0.0f;

    loadA(0); cpB(0, 0); stsA(0);
    asm volatile("cp.async.wait_group 0;\n");
    __syncthreads();

    #pragma unroll 1
    for (int ch = 0; ch < 24; ch++) {
        int s = ch & 1;
        if (ch + 1 < 24) { loadA(ch + 1); cpB(ch + 1, s ^ 1); }
        const unsigned* a = &sA[s][0];
        const unsigned* b = &sB[s][0];
        #pragma unroll
        for (int ks = 0; ks < 2; ks++) {
            int kb = ks * 8;
            unsigned af[4];
            int r0 = wid * 16 + g;
            af[0] = a[r0 * SPAD + kb + cc];
            af[1] = a[(r0 + 8) * SPAD + kb + cc];
            af[2] = a[r0 * SPAD + kb + cc + 4];
            af[3] = a[(r0 + 8) * SPAD + kb + cc + 4];
            unsigned bf[6][2];
            #pragma unroll
            for (int nt = 0; nt < 6; nt++) {
                int n = nt * 8 + g;
                bf[nt][0] = b[n * SPAD + kb + cc];
                bf[nt][1] = b[n * SPAD + kb + cc + 4];
            }
            #pragma unroll
            for (int nt = 0; nt < 6; nt++) MMA_TF32(acc[nt], af, bf[nt]);
        }
        if (ch + 1 < 24) {
            stsA(s ^ 1);
            asm volatile("cp.async.wait_group 0;\n");
            __syncthreads();
        }
    }

    // epilogue: frag (c0,c1) = (dy,dx) for k=4*nt+cc at row g; (c2,c3) at row g+8
    int loBase = mBase % LOUT;
    #pragma unroll
    for (int nt = 0; nt < 6; nt++) {
        int k = 4 * nt + cc;
        float bdy = __ldg(b_off + 8 * nt + 2 * cc);
        float bdx = __ldg(b_off + 8 * nt + 2 * cc + 1);
        #pragma unroll
        for (int half = 0; half < 2; half++) {
            int rr = wid * 16 + g + half * 8;
            int m  = mBase + rr;
            int lo = loBase + rr;
            float dy = acc[nt][half * 2 + 0] + bdy;
            float dx = acc[nt][half * 2 + 1] + bdx;
            float px = (float)(lo * Kn + k) + dx;
            float wy = fmaxf(0.0f, 1.0f - fabsf(dy));
            float x0 = floorf(px);
            float lw = px - x0;
            int i0 = (int)x0;
            bool valid = (px > -1.0f) && (px < (float)Ln);
            float w0 = (valid && i0 >= 0 && i0 < Ln) ? (1.0f - lw) * wy : 0.0f;
            float w1 = (valid && (i0 + 1) >= 0 && (i0 + 1) < Ln) ? lw * wy : 0.0f;
            int idx = m * Kn + k;
            g_i0[idx] = i0;
            g_w0[idx] = w0;
            g_w1[idx] = w1;
        }
    }
}

// ---------------- kernel 2: fused sample + tf32 GEMM ----------------
// A tile for chunk ch (= tap ch) built on the fly: val[m][ch*16+c] =
//   w0*x[b,a0,c] + w1*x[b,a1,c]. B = g_wdefT (pre-tf32) via cp.async.
__global__ __launch_bounds__(256, 2) void k_gemm_fused(const float* __restrict__ x,
                                                       const float* __restrict__ b_def,
                                                       float* __restrict__ out) {
    __shared__ unsigned sA[2][128 * SPAD];
    __shared__ unsigned sB[2][128 * SPAD];

    int tid = threadIdx.x, lane = tid & 31, wid = tid >> 5;
    int wm = wid & 3, wn = wid >> 2;
    int g = lane >> 2, cc = lane & 3;

    int mBase = blockIdx.y * 128;
    int nBase = blockIdx.x * 128;
    int bimg = mBase / LOUT;                         // 128 | LOUT, so constant per block
    const float* xb = x + (size_t)bimg * Ln * Cn;
    const unsigned* Bg = g_wdefT + (size_t)nBase * KDIM;

    int r = tid >> 1, h = tid & 1;                   // A staging row / channel half
    int m24 = (mBase + r) * Kn;

    int   nx_i0;  float nx_w0, nx_w1;                // meta for next chunk's x loads
    float4 u0, u1, v0, v1;                           // gathered x (raw, pre-lerp)
    float cw0, cw1;

    auto loadMeta = [&](int ch) {
        nx_i0 = g_i0[m24 + ch]; nx_w0 = g_w0[m24 + ch]; nx_w1 = g_w1[m24 + ch];
    };
    auto loadX = [&]() {
        int a0 = min(max(nx_i0, 0), Ln - 1);
        int a1 = min(max(nx_i0 + 1, 0), Ln - 1);
        const float4* p0 = (const float4*)(xb + (size_t)a0 * Cn + h * 8);
        const float4* p1 = (const float4*)(xb + (size_t)a1 * Cn + h * 8);
        u0 = p0[0]; u1 = p0[1];
        v0 = p1[0]; v1 = p1[1];
        cw0 = nx_w0; cw1 = nx_w1;
    };
    auto stsA = [&](int s) {
        unsigned* dst = &sA[s][r * SPAD + h * 8];
        uint4 q0, q1;
        q0.x = f2tf32(cw0 * u0.x + cw1 * v0.x);
        q0.y = f2tf32(cw0 * u0.y + cw1 * v0.y);
        q0.z = f2tf32(cw0 * u0.z + cw1 * v0.z);
        q0.w = f2tf32(cw0 * u0.w + cw1 * v0.w);
        q1.x = f2tf32(cw0 * u1.x + cw1 * v1.x);
        q1.y = f2tf32(cw0 * u1.y + cw1 * v1.y);
        q1.z = f2tf32(cw0 * u1.z + cw1 * v1.z);
        q1.w = f2tf32(cw0 * u1.w + cw1 * v1.w);
        *(uint4*)dst = q0;
        *(uint4*)(dst + 4) = q1;
    };
    auto cpB = [&](int ch, int s) {
        unsigned d = sptr(&sB[s][r * SPAD + h * 8]);
        const unsigned* src = Bg + (size_t)r * KDIM + ch * 16 + h * 8;
        asm volatile("cp.async.cg.shared.global [%0], [%1], 16;\n" :: "r"(d), "l"(src));
        asm volatile("cp.async.cg.shared.global [%0], [%1], 16;\n" :: "r"(d + 16), "l"(src + 4));
        asm volatile("cp.async.commit_group;\n");
    };

    float acc[2][8][4];
    #pragma unroll
    for (int i = 0; i < 2; i++)
        #pragma unroll
        for (int j = 0; j < 8; j++)
            #pragma unroll
            for (int q = 0; q < 4; q++) acc[i][j][q] = 0.0f;

    loadMeta(0);
    loadX();
    cpB(0, 0);
    loadMeta(1);
    stsA(0);
    asm volatile("cp.async.wait_group 0;\n");
    __syncthreads();

    #pragma unroll 1
    for (int ch = 0; ch < 24; ch++) {
        int s = ch & 1;
        if (ch + 1 < 24) {
            loadX();                     // consumes meta(ch+1)
            cpB(ch + 1, s ^ 1);
            if (ch + 2 < 24) loadMeta(ch + 2);
        }
        const unsigned* a = &sA[s][0];
        const unsigned* b = &sB[s][0];
        #pragma unroll
        for (int ks = 0; ks < 2; ks++) {
            int kb = ks * 8;
            unsigned af[2][4];
            #pragma unroll
            for (int mt = 0; mt < 2; mt++) {
                int r0 = wm * 32 + mt * 16 + g;
                af[mt][0] = a[r0 * SPAD + kb + cc];
                af[mt][1] = a[(r0 + 8) * SPAD + kb + cc];
                af[mt][2] = a[r0 * SPAD + kb + cc + 4];
                af[mt][3] = a[(r0 + 8) * SPAD + kb + cc + 4];
            }
            unsigned bf[8][2];
            #pragma unroll
            for (int nt = 0; nt < 8; nt++) {
                int n = wn * 64 + nt * 8 + g;
                bf[nt][0] = b[n * SPAD + kb + cc];
                bf[nt][1] = b[n * SPAD + kb + cc + 4];
            }
            #pragma unroll
            for (int mt = 0; mt < 2; mt++)
                #pragma unroll
                for (int nt = 0; nt < 8; nt++) MMA_TF32(acc[mt][nt], af[mt], bf[nt]);
        }
        if (ch + 1 < 24) {
            stsA(s ^ 1);
            asm volatile("cp.async.wait_group 0;\n");
            __syncthreads();
        }
    }

    // epilogue
    #pragma unroll
    for (int mt = 0; mt < 2; mt++) {
        int r0 = mBase + wm * 32 + mt * 16 + g;
        #pragma unroll
        for (int nt = 0; nt < 8; nt++) {
            int col = nBase + wn * 64 + nt * 8 + 2 * cc;
            float bz0 = __ldg(b_def + col);
            float bz1 = __ldg(b_def + col + 1);
            float2 o0 = make_float2(acc[mt][nt][0] + bz0, acc[mt][nt][1] + bz1);
            float2 o1 = make_float2(acc[mt][nt][2] + bz0, acc[mt][nt][3] + bz1);
            *(float2*)(out + (size_t)r0 * Dn + col) = o0;
            *(float2*)(out + (size_t)(r0 + 8) * Dn + col) = o1;
        }
    }
}

// ---------------- launch ----------------
extern "C" void kernel_launch(void* const* d_in, const int* in_sizes, int n_in,
                              void* d_out, int out_size) {
    const float* x     = (const float*)d_in[0];
    const float* w_off = (const float*)d_in[1];
    const float* b_off = (const float*)d_in[2];
    const float* w_def = (const float*)d_in[3];
    const float* b_def = (const float*)d_in[4];
    float* out = (float*)d_out;

    (void)in_sizes; (void)n_in; (void)out_size;

    k_prep<<<(48 * KDIM + Dn * KDIM) / 256, 256>>>(w_off, w_def);
    k_offsets_tc<<<Mtot / 128, 256>>>(x, b_off);
    k_gemm_fused<<<dim3(Dn / 128, Mtot / 128), 256>>>(x, b_def, out);
}